// round 12
// baseline (speedup 1.0000x reference)
#include <cuda_runtime.h>
#include <math.h>
#include <stdint.h>

#define NE     128
#define NC     256
#define TILE_M 64
#define BLK    512
#define GRID   148

// smem: AB (swizzled uint2 hi/lo, pad-free) + cst (separate, stride 296: ≡8 mod 32
// -> the 4 groups of a warp hit disjoint bank octets during LU loads)
#define SM_AB    0            // 64*128*8 = 65536
#define SM_CST   65536        // 64*296*4 = 75776
#define CST_MAT  296
#define SMEM_BYTES 141312

__device__ __forceinline__ uint32_t f2tf(float x) {
    uint32_t r;
    asm("cvt.rna.tf32.f32 %0, %1;" : "=r"(r) : "f"(x));
    return r;
}

#define MMA_TF32(c, a, b0, b1) \
    asm volatile("mma.sync.aligned.m16n8k8.row.col.f32.tf32.tf32.f32 " \
        "{%0,%1,%2,%3}, {%4,%5,%6,%7}, {%8,%9}, {%0,%1,%2,%3};" \
        : "+f"((c)[0]), "+f"((c)[1]), "+f"((c)[2]), "+f"((c)[3]) \
        : "r"((a)[0]), "r"((a)[1]), "r"((a)[2]), "r"((a)[3]), "r"(b0), "r"(b1))

__global__ __launch_bounds__(BLK, 1)
void jastrow_lu8_kernel(const float* __restrict__ occ,
                        const float* __restrict__ W,
                        const float* __restrict__ bias,
                        float* __restrict__ out,
                        int B)
{
    extern __shared__ char sm[];
    uint2* AB  = (uint2*)(sm + SM_AB);
    float* cst = (float*)(sm + SM_CST);

    const int tid  = threadIdx.x;
    const int wid  = tid >> 5;       // 0..15 : 16-col strip of W
    const int lane = tid & 31;
    const int lq   = lane >> 2;      // 0..7
    const int lr   = lane & 3;       // 0..3
    const int wg   = lane >> 3;      // 0..3 : 8-lane group within warp (LU)
    const int gl   = lane & 7;       // lane within group (LU)

    // ---- W fragment permanently in registers: 64 fp32 per thread ----
    float wreg[64];
    #pragma unroll
    for (int ks = 0; ks < 16; ks++)
        #pragma unroll
        for (int j = 0; j < 4; j++) {
            int k = ks * 8 + lr + ((j >> 1) << 2);
            int c = wid * 16 + lq + ((j & 1) << 3);
            wreg[ks * 4 + j] = W[k * NC + c];
        }
    const float bias0 = bias[wid * 16 + lq];
    const float bias1 = bias[wid * 16 + lq + 8];

    const int ntiles = B / TILE_M;

    // ---- prologue: fill AB for first tile ----
    {
        const int m0 = blockIdx.x * TILE_M;
        #pragma unroll
        for (int it = 0; it < 8; it++) {
            int i = tid + it * BLK;
            int m = i >> 6;
            int k = (i & 63) * 2;
            float2 v = *(const float2*)(occ + (size_t)(m0 + m) * NE + k);
            uint32_t xh = f2tf(v.x);
            uint32_t xl = f2tf(v.x - __uint_as_float(xh));
            uint32_t yh = f2tf(v.y);
            uint32_t yl = f2tf(v.y - __uint_as_float(yh));
            int idx2 = m * 128 + (k ^ ((m & 7) << 2));
            *(uint4*)&AB[idx2] = make_uint4(xh, xl, yh, yl);
        }
    }
    __syncthreads();

    for (int tile = blockIdx.x; tile < ntiles; tile += GRID) {
        const int m0 = tile * TILE_M;
        const int pnext = (tile + GRID < ntiles) ? tile + GRID : tile;

        // ---- GEMM: warp wid -> W cols wid*16..+15 (m), all 64 batch rows (n) ----
        float acc[8][4];
        #pragma unroll
        for (int t = 0; t < 8; t++)
            #pragma unroll
            for (int e = 0; e < 4; e++) acc[t][e] = 0.f;

        #pragma unroll
        for (int ks = 0; ks < 16; ks++) {
            uint32_t wh[4], wl[4];
            #pragma unroll
            for (int j = 0; j < 4; j++) {
                float f = wreg[ks * 4 + j];
                wh[j] = f2tf(f);
                wl[j] = f2tf(f - __uint_as_float(wh[j]));
            }
            const int q = (ks * 8 + lr) ^ (lq << 2);   // swizzled k-index
            #pragma unroll
            for (int t = 0; t < 8; t++) {
                const int ar0 = (t * 8 + lq) * 128 + q;
                uint2 p0 = AB[ar0];          // {hi,lo} of element (row, kb)
                uint2 p1 = AB[ar0 ^ 4];      // {hi,lo} of element (row, kb+4)
                MMA_TF32(acc[t], wh, p0.x, p1.x);   // Whi * Ahi
                MMA_TF32(acc[t], wh, p0.y, p1.y);   // Whi * Alo
                MMA_TF32(acc[t], wl, p0.x, p1.x);   // Wlo * Ahi
            }
        }

        // ---- prefetch next tile's occ rows (latency hidden by stage+LU) ----
        float2 pf[8];
        #pragma unroll
        for (int it = 0; it < 8; it++) {
            int i = tid + it * BLK;
            int m = i >> 6;
            int k = (i & 63) * 2;
            pf[it] = *(const float2*)(occ + (size_t)(pnext * TILE_M + m) * NE + k);
        }

        // ---- stage all 64 matrices into cst ----
        #pragma unroll
        for (int t = 0; t < 8; t++) {
            #pragma unroll
            for (int e = 0; e < 4; e++) {
                int c = wid * 16 + lq + ((e >> 1) << 3);
                int r = t * 8 + 2 * lr + (e & 1);
                float bv = (e >> 1) ? bias1 : bias0;
                // j element (rr=c>>4, cc=c&15) -> [mat r][rr*17 + cc]
                cst[r * CST_MAT + (c >> 4) * 17 + (c & 15)] = acc[t][e] + bv;
            }
        }
        __syncthreads();   // cst complete; all GEMM AB reads also done

        // ---- 8-lane LU: group (wid,wg) owns matrix mat; lane gl holds rows gl, gl+8 ----
        {
            const int mat = wid * 4 + wg;
            float a0[16], a1[16];
            #pragma unroll
            for (int k = 0; k < 16; k++) {
                a0[k] = cst[mat * CST_MAT + k * 17 + gl]     + (k == gl     ? 1.f : 0.f);
                a1[k] = cst[mat * CST_MAT + k * 17 + gl + 8] + (k == gl + 8 ? 1.f : 0.f);
            }

            bool  done0 = false, done1 = false;
            float mylog = 0.f;
            int   mysgn = 1;
            int   pick0 = 0, pick1 = 0;

            #pragma unroll
            for (int k = 0; k < 16; k++) {
                // packed argmax over 16 rows: |v| bits (low 4 masked) | (15-row)
                uint32_t u0 = done0 ? 0u
                    : ((__float_as_uint(fabsf(a0[k])) & ~0xFu) | (uint32_t)(15 - gl));
                uint32_t u1 = done1 ? 0u
                    : ((__float_as_uint(fabsf(a1[k])) & ~0xFu) | (uint32_t)(7 - gl));
                uint32_t u = (u0 > u1) ? u0 : u1;
                #pragma unroll
                for (int off = 4; off; off >>= 1) {
                    uint32_t o = __shfl_xor_sync(0xffffffffu, u, off, 8);
                    u = (o > u) ? o : u;
                }
                const int   p    = 15 - (int)(u & 15u);   // pivot row 0..15
                const float vsel = (p < 8) ? a0[k] : a1[k];
                const float piv  = __shfl_sync(0xffffffffu, vsel, p & 7, 8);
                const bool  imp0 = (p == gl);
                const bool  imp1 = (p == gl + 8);
                const float m0v  = (!done0 && !imp0) ? (a0[k] / piv) : 0.f;
                const float m1v  = (!done1 && !imp1) ? (a1[k] / piv) : 0.f;
                #pragma unroll
                for (int jj = k + 1; jj < 16; jj++) {
                    float wsel = (p < 8) ? a0[jj] : a1[jj];
                    float pr = __shfl_sync(0xffffffffu, wsel, p & 7, 8);
                    a0[jj] -= m0v * pr;
                    a1[jj] -= m1v * pr;
                }
                if (imp0) {
                    done0 = true; pick0 = k;
                    mylog += logf(fabsf(piv));
                    if (piv < 0.f) mysgn = -mysgn;
                }
                if (imp1) {
                    done1 = true; pick1 = k;
                    mylog += logf(fabsf(piv));
                    if (piv < 0.f) mysgn = -mysgn;
                }
            }

            // permutation parity: inversions of (row -> pick step)
            int inv = 0;
            #pragma unroll
            for (int t = 0; t < 16; t++) {
                int pv = (t < 8) ? pick0 : pick1;
                int pt = __shfl_sync(0xffffffffu, pv, t & 7, 8);
                inv += (t < gl     && pt > pick0) ? 1 : 0;
                inv += (t < gl + 8 && pt > pick1) ? 1 : 0;
            }

            // width-8 reductions
            float logsum = mylog;
            int   invsum = inv;
            int   sgn    = mysgn;
            #pragma unroll
            for (int off = 4; off; off >>= 1) {
                logsum += __shfl_xor_sync(0xffffffffu, logsum, off, 8);
                invsum += __shfl_xor_sync(0xffffffffu, invsum, off, 8);
                sgn    *= __shfl_xor_sync(0xffffffffu, sgn,    off, 8);
            }

            if (gl == 0) {
                const int g = m0 + mat;
                out[g]     = (float)sgn * ((invsum & 1) ? -1.f : 1.f);
                out[B + g] = logsum;
            }
        }

        // ---- split + store prefetched next tile into AB ----
        #pragma unroll
        for (int it = 0; it < 8; it++) {
            int i = tid + it * BLK;
            int m = i >> 6;
            int k = (i & 63) * 2;
            float2 v = pf[it];
            uint32_t xh = f2tf(v.x);
            uint32_t xl = f2tf(v.x - __uint_as_float(xh));
            uint32_t yh = f2tf(v.y);
            uint32_t yl = f2tf(v.y - __uint_as_float(yh));
            int idx2 = m * 128 + (k ^ ((m & 7) << 2));
            *(uint4*)&AB[idx2] = make_uint4(xh, xl, yh, yl);
        }
        __syncthreads();   // AB(n+1) ready; cst reusable
    }
}

extern "C" void kernel_launch(void* const* d_in, const int* in_sizes, int n_in,
                              void* d_out, int out_size)
{
    const float* occ  = (const float*)d_in[0];   // (B, 128) fp32
    const float* W    = (const float*)d_in[1];   // (128, 256) fp32
    const float* bias = (const float*)d_in[2];   // (256,) fp32
    float* out        = (float*)d_out;           // [sign(B); logabs(B)]
    const int B = in_sizes[0] / NE;

    cudaFuncSetAttribute(jastrow_lu8_kernel,
                         cudaFuncAttributeMaxDynamicSharedMemorySize, SMEM_BYTES);
    jastrow_lu8_kernel<<<GRID, BLK, SMEM_BYTES>>>(occ, W, bias, out, B);
}

// round 14
// speedup vs baseline: 1.4128x; 1.4128x over previous
#include <cuda_runtime.h>
#include <math.h>
#include <stdint.h>

#define NE     128
#define NC     256
#define TILE_M 64
#define BLK    512
#define GRID   148

// smem (bytes): W swizzled pad-free | A fp32 swizzled | cst stride-260
#define SM_W     0              // 256*128*4 = 131072
#define SM_A     131072         // 64*128*4  = 32768
#define SM_CST   163840         // 64*260*4  = 66560
#define CST_MAT  260
#define SMEM_BYTES 230400

__device__ __forceinline__ uint32_t f2tf(float x) {
    uint32_t r;
    asm("cvt.rna.tf32.f32 %0, %1;" : "=r"(r) : "f"(x));
    return r;
}

#define MMA_TF32(c, a, b0, b1) \
    asm volatile("mma.sync.aligned.m16n8k8.row.col.f32.tf32.tf32.f32 " \
        "{%0,%1,%2,%3}, {%4,%5,%6,%7}, {%8,%9}, {%0,%1,%2,%3};" \
        : "+f"((c)[0]), "+f"((c)[1]), "+f"((c)[2]), "+f"((c)[3]) \
        : "r"((a)[0]), "r"((a)[1]), "r"((a)[2]), "r"((a)[3]), "r"(b0), "r"(b1))

__global__ __launch_bounds__(BLK, 1)
void jastrow_fused_kernel(const float* __restrict__ occ,
                          const float* __restrict__ W,
                          const float* __restrict__ bias,
                          float* __restrict__ out,
                          int B)
{
    extern __shared__ char sm[];
    float* Wsh = (float*)(sm + SM_W);
    float* Ash = (float*)(sm + SM_A);
    float* cst = (float*)(sm + SM_CST);

    const int tid  = threadIdx.x;
    const int wid  = tid >> 5;       // 0..15 : 16-col strip of W
    const int lane = tid & 31;
    const int lq   = lane >> 2;      // 0..7
    const int lr   = lane & 3;       // 0..3
    const int hw   = tid >> 4;       // half-warp 0..31 (LU: matrices 2hw, 2hw+1)
    const int l    = tid & 15;       // lane in half-warp (LU)

    // ---- load W into smem once (swizzled, pad-free) ----
    for (int i = tid; i < NE * NC; i += BLK) {
        int k = i >> 8;
        int c = i & 255;
        Wsh[c * 128 + (k ^ ((c & 7) << 2))] = W[k * NC + c];
    }
    const float bias0 = bias[wid * 16 + lq];
    const float bias1 = bias[wid * 16 + lq + 8];

    const int ntiles = B / TILE_M;

    // ---- prologue: fill A for first tile ----
    {
        const int m0 = blockIdx.x * TILE_M;
        #pragma unroll
        for (int it = 0; it < 8; it++) {
            int i = tid + it * BLK;
            int m = i >> 6;
            int k2 = (i & 63) * 2;
            float2 v = *(const float2*)(occ + (size_t)(m0 + m) * NE + k2);
            int idx = m * 128 + (k2 ^ ((m & 7) << 2));
            *(float2*)&Ash[idx] = v;
        }
    }
    __syncthreads();

    int prev_m0 = -1;

    for (int tile = blockIdx.x; tile < ntiles; tile += GRID) {
        const int m0 = tile * TILE_M;
        const int nxt = (tile + GRID < ntiles) ? tile + GRID : tile;

        // ---- top: load LU operands of PREVIOUS tile from cst (garbage on first iter) ----
        float a[16], b[16];
        #pragma unroll
        for (int k = 0; k < 16; k++) {
            float d = (k == l) ? 1.f : 0.f;
            a[k] = cst[(2 * hw)     * CST_MAT + k * 16 + l] + d;
            b[k] = cst[(2 * hw + 1) * CST_MAT + k * 16 + l] + d;
        }

        float acc[8][4];
        #pragma unroll
        for (int t = 0; t < 8; t++)
            #pragma unroll
            for (int e = 0; e < 4; e++) acc[t][e] = 0.f;

        bool  doneA = false,  doneB = false;
        float logA  = 0.f,    logB  = 0.f;
        int   sgnA  = 1,      sgnB  = 1;
        int   pickA = 0,      pickB = 0;

        // ---- FUSED loop: GEMM(tile n) ks-step + LU(tile n-1) pivot-step k=ks ----
        #pragma unroll
        for (int ks = 0; ks < 16; ks++) {
            // --- GEMM part ---
            uint32_t wh[4], wl[4];
            #pragma unroll
            for (int j = 0; j < 4; j++) {
                int k = ks * 8 + lr + ((j >> 1) << 2);
                int c = wid * 16 + lq + ((j & 1) << 3);
                float f = Wsh[c * 128 + (k ^ (lq << 2))];   // c&7 == lq
                wh[j] = f2tf(f);
                wl[j] = f2tf(f - __uint_as_float(wh[j]));
            }
            const int q = (ks * 8 + lr) ^ (lq << 2);
            #pragma unroll
            for (int t = 0; t < 8; t++) {
                const int ar0 = (t * 8 + lq) * 128 + q;
                float f0 = Ash[ar0];
                float f1 = Ash[ar0 ^ 4];
                uint32_t h0 = f2tf(f0), h1 = f2tf(f1);
                uint32_t l0 = f2tf(f0 - __uint_as_float(h0));
                uint32_t l1 = f2tf(f1 - __uint_as_float(h1));
                MMA_TF32(acc[t], wh, h0, h1);   // Whi * Ahi
                MMA_TF32(acc[t], wh, l0, l1);   // Whi * Alo
                MMA_TF32(acc[t], wl, h0, h1);   // Wlo * Ahi
            }

            // --- LU pivot step k = ks (independent of GEMM regs; ptxas interleaves) ---
            {
                const int k = ks;
                uint32_t uA = doneA ? 0u
                    : ((__float_as_uint(fabsf(a[k])) & ~0xFu) | (15u - (uint32_t)l));
                uint32_t uB = doneB ? 0u
                    : ((__float_as_uint(fabsf(b[k])) & ~0xFu) | (15u - (uint32_t)l));
                #pragma unroll
                for (int off = 8; off; off >>= 1) {
                    uint32_t oA = __shfl_xor_sync(0xffffffffu, uA, off, 16);
                    uint32_t oB = __shfl_xor_sync(0xffffffffu, uB, off, 16);
                    uA = (oA > uA) ? oA : uA;
                    uB = (oB > uB) ? oB : uB;
                }
                const int   pA   = 15 - (int)(uA & 15u);
                const int   pB   = 15 - (int)(uB & 15u);
                const float pivA = __shfl_sync(0xffffffffu, a[k], pA, 16);
                const float pivB = __shfl_sync(0xffffffffu, b[k], pB, 16);
                const bool  impA = (l == pA);
                const bool  impB = (l == pB);
                const float mulA = (!doneA && !impA) ? (a[k] / pivA) : 0.f;
                const float mulB = (!doneB && !impB) ? (b[k] / pivB) : 0.f;
                #pragma unroll
                for (int jj = k + 1; jj < 16; jj++) {
                    float prA = __shfl_sync(0xffffffffu, a[jj], pA, 16);
                    float prB = __shfl_sync(0xffffffffu, b[jj], pB, 16);
                    a[jj] -= mulA * prA;
                    b[jj] -= mulB * prB;
                }
                if (impA) {
                    doneA = true; pickA = k;
                    logA += logf(fabsf(pivA));
                    if (pivA < 0.f) sgnA = -sgnA;
                }
                if (impB) {
                    doneB = true; pickB = k;
                    logB += logf(fabsf(pivB));
                    if (pivB < 0.f) sgnB = -sgnB;
                }
            }
        }

        // ---- LU post: parity + reductions + store (skip on first iteration) ----
        {
            int invA = 0, invB = 0;
            #pragma unroll
            for (int t = 0; t < 16; t++) {
                int ptA = __shfl_sync(0xffffffffu, pickA, t, 16);
                int ptB = __shfl_sync(0xffffffffu, pickB, t, 16);
                invA += (t < l && ptA > pickA) ? 1 : 0;
                invB += (t < l && ptB > pickB) ? 1 : 0;
            }
            #pragma unroll
            for (int off = 8; off; off >>= 1) {
                logA += __shfl_xor_sync(0xffffffffu, logA, off, 16);
                logB += __shfl_xor_sync(0xffffffffu, logB, off, 16);
                invA += __shfl_xor_sync(0xffffffffu, invA, off, 16);
                invB += __shfl_xor_sync(0xffffffffu, invB, off, 16);
                sgnA *= __shfl_xor_sync(0xffffffffu, sgnA, off, 16);
                sgnB *= __shfl_xor_sync(0xffffffffu, sgnB, off, 16);
            }
            if (l == 0 && prev_m0 >= 0) {
                const int g = prev_m0 + 2 * hw;
                out[g]         = (float)sgnA * ((invA & 1) ? -1.f : 1.f);
                out[g + 1]     = (float)sgnB * ((invB & 1) ? -1.f : 1.f);
                out[B + g]     = logA;
                out[B + g + 1] = logB;
            }
        }

        __syncthreads();   // all cst top-loads + all A reads complete

        // ---- stage acc -> cst (conflict-free via stride 260) ----
        #pragma unroll
        for (int t = 0; t < 8; t++) {
            #pragma unroll
            for (int e = 0; e < 4; e++) {
                int c = wid * 16 + lq + ((e >> 1) << 3);
                int r = t * 8 + 2 * lr + (e & 1);
                float bv = (e >> 1) ? bias1 : bias0;
                cst[r * CST_MAT + (c >> 4) * 16 + (c & 15)] = acc[t][e] + bv;
            }
        }

        // ---- fill A for next tile ----
        {
            const int nm0 = nxt * TILE_M;
            #pragma unroll
            for (int it = 0; it < 8; it++) {
                int i = tid + it * BLK;
                int m = i >> 6;
                int k2 = (i & 63) * 2;
                float2 v = *(const float2*)(occ + (size_t)(nm0 + m) * NE + k2);
                int idx = m * 128 + (k2 ^ ((m & 7) << 2));
                *(float2*)&Ash[idx] = v;
            }
        }

        prev_m0 = m0;
        __syncthreads();   // cst(n) + A(n+1) ready
    }

    // ---- epilogue: LU of the LAST tile (cst holds it; prev_m0 = last m0) ----
    if (prev_m0 >= 0) {
        float a[16], b[16];
        #pragma unroll
        for (int k = 0; k < 16; k++) {
            float d = (k == l) ? 1.f : 0.f;
            a[k] = cst[(2 * hw)     * CST_MAT + k * 16 + l] + d;
            b[k] = cst[(2 * hw + 1) * CST_MAT + k * 16 + l] + d;
        }
        bool  doneA = false,  doneB = false;
        float logA  = 0.f,    logB  = 0.f;
        int   sgnA  = 1,      sgnB  = 1;
        int   pickA = 0,      pickB = 0;
        #pragma unroll
        for (int k = 0; k < 16; k++) {
            uint32_t uA = doneA ? 0u
                : ((__float_as_uint(fabsf(a[k])) & ~0xFu) | (15u - (uint32_t)l));
            uint32_t uB = doneB ? 0u
                : ((__float_as_uint(fabsf(b[k])) & ~0xFu) | (15u - (uint32_t)l));
            #pragma unroll
            for (int off = 8; off; off >>= 1) {
                uint32_t oA = __shfl_xor_sync(0xffffffffu, uA, off, 16);
                uint32_t oB = __shfl_xor_sync(0xffffffffu, uB, off, 16);
                uA = (oA > uA) ? oA : uA;
                uB = (oB > uB) ? oB : uB;
            }
            const int   pA   = 15 - (int)(uA & 15u);
            const int   pB   = 15 - (int)(uB & 15u);
            const float pivA = __shfl_sync(0xffffffffu, a[k], pA, 16);
            const float pivB = __shfl_sync(0xffffffffu, b[k], pB, 16);
            const bool  impA = (l == pA);
            const bool  impB = (l == pB);
            const float mulA = (!doneA && !impA) ? (a[k] / pivA) : 0.f;
            const float mulB = (!doneB && !impB) ? (b[k] / pivB) : 0.f;
            #pragma unroll
            for (int jj = k + 1; jj < 16; jj++) {
                float prA = __shfl_sync(0xffffffffu, a[jj], pA, 16);
                float prB = __shfl_sync(0xffffffffu, b[jj], pB, 16);
                a[jj] -= mulA * prA;
                b[jj] -= mulB * prB;
            }
            if (impA) {
                doneA = true; pickA = k;
                logA += logf(fabsf(pivA));
                if (pivA < 0.f) sgnA = -sgnA;
            }
            if (impB) {
                doneB = true; pickB = k;
                logB += logf(fabsf(pivB));
                if (pivB < 0.f) sgnB = -sgnB;
            }
        }
        int invA = 0, invB = 0;
        #pragma unroll
        for (int t = 0; t < 16; t++) {
            int ptA = __shfl_sync(0xffffffffu, pickA, t, 16);
            int ptB = __shfl_sync(0xffffffffu, pickB, t, 16);
            invA += (t < l && ptA > pickA) ? 1 : 0;
            invB += (t < l && ptB > pickB) ? 1 : 0;
        }
        #pragma unroll
        for (int off = 8; off; off >>= 1) {
            logA += __shfl_xor_sync(0xffffffffu, logA, off, 16);
            logB += __shfl_xor_sync(0xffffffffu, logB, off, 16);
            invA += __shfl_xor_sync(0xffffffffu, invA, off, 16);
            invB += __shfl_xor_sync(0xffffffffu, invB, off, 16);
            sgnA *= __shfl_xor_sync(0xffffffffu, sgnA, off, 16);
            sgnB *= __shfl_xor_sync(0xffffffffu, sgnB, off, 16);
        }
        if (l == 0) {
            const int g = prev_m0 + 2 * hw;
            out[g]         = (float)sgnA * ((invA & 1) ? -1.f : 1.f);
            out[g + 1]     = (float)sgnB * ((invB & 1) ? -1.f : 1.f);
            out[B + g]     = logA;
            out[B + g + 1] = logB;
        }
    }
}

extern "C" void kernel_launch(void* const* d_in, const int* in_sizes, int n_in,
                              void* d_out, int out_size)
{
    const float* occ  = (const float*)d_in[0];   // (B, 128) fp32
    const float* W    = (const float*)d_in[1];   // (128, 256) fp32
    const float* bias = (const float*)d_in[2];   // (256,) fp32
    float* out        = (float*)d_out;           // [sign(B); logabs(B)]
    const int B = in_sizes[0] / NE;

    cudaFuncSetAttribute(jastrow_fused_kernel,
                         cudaFuncAttributeMaxDynamicSharedMemorySize, SMEM_BYTES);
    jastrow_fused_kernel<<<GRID, BLK, SMEM_BYTES>>>(occ, W, bias, out, B);
}

// round 16
// speedup vs baseline: 1.6065x; 1.1371x over previous
#include <cuda_runtime.h>
#include <math.h>
#include <stdint.h>

#define NE     128
#define NC     256
#define TILE_M 64
#define BLK    512
#define GRID   148

// smem: AB pre-split uint2 {hi,lo} swizzled | cst stride-260 (conflict-free)
#define SM_AB    0              // 64*128*8 = 65536
#define SM_CST   65536          // 64*260*4 = 66560
#define CST_MAT  260
#define SMEM_BYTES 132096

__device__ __forceinline__ uint32_t f2tf(float x) {
    uint32_t r;
    asm("cvt.rna.tf32.f32 %0, %1;" : "=r"(r) : "f"(x));
    return r;
}

#define MMA_TF32(c, a, b0, b1) \
    asm volatile("mma.sync.aligned.m16n8k8.row.col.f32.tf32.tf32.f32 " \
        "{%0,%1,%2,%3}, {%4,%5,%6,%7}, {%8,%9}, {%0,%1,%2,%3};" \
        : "+f"((c)[0]), "+f"((c)[1]), "+f"((c)[2]), "+f"((c)[3]) \
        : "r"((a)[0]), "r"((a)[1]), "r"((a)[2]), "r"((a)[3]), "r"(b0), "r"(b1))

__global__ __launch_bounds__(BLK, 1)
void jastrow_f2_kernel(const float* __restrict__ occ,
                       const float* __restrict__ W,
                       const float* __restrict__ bias,
                       float* __restrict__ out,
                       int B)
{
    extern __shared__ char sm[];
    uint2* AB  = (uint2*)(sm + SM_AB);
    float* cst = (float*)(sm + SM_CST);

    const int tid  = threadIdx.x;
    const int wid  = tid >> 5;       // 0..15 : 16-col strip of W
    const int lane = tid & 31;
    const int lq   = lane >> 2;      // 0..7
    const int lr   = lane & 3;       // 0..3
    const int hw   = tid >> 4;       // half-warp 0..31 (LU: matrices 2hw, 2hw+1)
    const int l    = tid & 15;       // lane in half-warp (LU)

    // per-thread W base: element (k = lr + ..., c = wid*16 + lq + ...)
    const float* Wb = W + lr * NC + wid * 16 + lq;
    const float bias0 = bias[wid * 16 + lq];
    const float bias1 = bias[wid * 16 + lq + 8];

    const int ntiles = B / TILE_M;

    // ---- prologue: fill AB (pre-split tf32 {hi,lo}) for first tile ----
    {
        const int m0 = blockIdx.x * TILE_M;
        #pragma unroll
        for (int it = 0; it < 8; it++) {
            int i = tid + it * BLK;
            int m = i >> 6;
            int k2 = (i & 63) * 2;
            float2 v = *(const float2*)(occ + (size_t)(m0 + m) * NE + k2);
            uint32_t xh = f2tf(v.x);
            uint32_t xl = f2tf(v.x - __uint_as_float(xh));
            uint32_t yh = f2tf(v.y);
            uint32_t yl = f2tf(v.y - __uint_as_float(yh));
            int idx = m * 128 + (k2 ^ ((m & 7) << 2));
            *(uint4*)&AB[idx] = make_uint4(xh, xl, yh, yl);
        }
    }
    __syncthreads();

    int prev_m0 = -1;

    for (int tile = blockIdx.x; tile < ntiles; tile += GRID) {
        const int m0 = tile * TILE_M;
        const int nxt = (tile + GRID < ntiles) ? tile + GRID : tile;

        // ---- top: load LU operands of PREVIOUS tile from cst (garbage on first iter) ----
        float a[16], b[16];
        #pragma unroll
        for (int k = 0; k < 16; k++) {
            float d = (k == l) ? 1.f : 0.f;
            a[k] = cst[(2 * hw)     * CST_MAT + k * 16 + l] + d;
            b[k] = cst[(2 * hw + 1) * CST_MAT + k * 16 + l] + d;
        }

        float acc[8][4];
        #pragma unroll
        for (int t = 0; t < 8; t++)
            #pragma unroll
            for (int e = 0; e < 4; e++) acc[t][e] = 0.f;

        bool  doneA = false,  doneB = false;
        float logA  = 0.f,    logB  = 0.f;
        int   sgnA  = 1,      sgnB  = 1;
        int   pickA = 0,      pickB = 0;

        // W fragment prefetch for ks=0
        float wf[4];
        wf[0] = Wb[0];
        wf[1] = Wb[8];
        wf[2] = Wb[1024];
        wf[3] = Wb[1032];

        // ---- FUSED loop: GEMM(tile n) ks-step + LU(tile n-1) pivot-step k=ks ----
        #pragma unroll
        for (int ks = 0; ks < 16; ks++) {
            // prefetch next ks's W fragment (L2-resident; hidden under this ks's work)
            float wn[4];
            if (ks < 15) {
                const float* p = Wb + (ks + 1) * (8 * NC);
                wn[0] = p[0];
                wn[1] = p[8];
                wn[2] = p[1024];
                wn[3] = p[1032];
            }

            // --- GEMM part ---
            uint32_t wh[4], wl[4];
            #pragma unroll
            for (int j = 0; j < 4; j++) {
                wh[j] = f2tf(wf[j]);
                wl[j] = f2tf(wf[j] - __uint_as_float(wh[j]));
            }
            const int q = (ks * 8 + lr) ^ (lq << 2);
            #pragma unroll
            for (int t = 0; t < 8; t++) {
                const int ar0 = (t * 8 + lq) * 128 + q;
                uint2 p0 = AB[ar0];          // {hi,lo} of element (row, kb)
                uint2 p1 = AB[ar0 ^ 4];      // {hi,lo} of element (row, kb+4)
                MMA_TF32(acc[t], wh, p0.x, p1.x);   // Whi * Ahi
                MMA_TF32(acc[t], wh, p0.y, p1.y);   // Whi * Alo
                MMA_TF32(acc[t], wl, p0.x, p1.x);   // Wlo * Ahi
            }

            // --- LU pivot step k = ks (register-independent; interleaves with MMAs) ---
            {
                const int k = ks;
                uint32_t uA = doneA ? 0u
                    : ((__float_as_uint(fabsf(a[k])) & ~0xFu) | (15u - (uint32_t)l));
                uint32_t uB = doneB ? 0u
                    : ((__float_as_uint(fabsf(b[k])) & ~0xFu) | (15u - (uint32_t)l));
                #pragma unroll
                for (int off = 8; off; off >>= 1) {
                    uint32_t oA = __shfl_xor_sync(0xffffffffu, uA, off, 16);
                    uint32_t oB = __shfl_xor_sync(0xffffffffu, uB, off, 16);
                    uA = (oA > uA) ? oA : uA;
                    uB = (oB > uB) ? oB : uB;
                }
                const int   pA   = 15 - (int)(uA & 15u);
                const int   pB   = 15 - (int)(uB & 15u);
                const float pivA = __shfl_sync(0xffffffffu, a[k], pA, 16);
                const float pivB = __shfl_sync(0xffffffffu, b[k], pB, 16);
                const bool  impA = (l == pA);
                const bool  impB = (l == pB);
                const float mulA = (!doneA && !impA) ? (a[k] / pivA) : 0.f;
                const float mulB = (!doneB && !impB) ? (b[k] / pivB) : 0.f;
                #pragma unroll
                for (int jj = k + 1; jj < 16; jj++) {
                    float prA = __shfl_sync(0xffffffffu, a[jj], pA, 16);
                    float prB = __shfl_sync(0xffffffffu, b[jj], pB, 16);
                    a[jj] -= mulA * prA;
                    b[jj] -= mulB * prB;
                }
                if (impA) {
                    doneA = true; pickA = k;
                    logA += logf(fabsf(pivA));
                    if (pivA < 0.f) sgnA = -sgnA;
                }
                if (impB) {
                    doneB = true; pickB = k;
                    logB += logf(fabsf(pivB));
                    if (pivB < 0.f) sgnB = -sgnB;
                }
            }

            #pragma unroll
            for (int j = 0; j < 4; j++) wf[j] = wn[j];
        }

        // ---- LU post: parity + reductions + store (skip on first iteration) ----
        {
            int invA = 0, invB = 0;
            #pragma unroll
            for (int t = 0; t < 16; t++) {
                int ptA = __shfl_sync(0xffffffffu, pickA, t, 16);
                int ptB = __shfl_sync(0xffffffffu, pickB, t, 16);
                invA += (t < l && ptA > pickA) ? 1 : 0;
                invB += (t < l && ptB > pickB) ? 1 : 0;
            }
            #pragma unroll
            for (int off = 8; off; off >>= 1) {
                logA += __shfl_xor_sync(0xffffffffu, logA, off, 16);
                logB += __shfl_xor_sync(0xffffffffu, logB, off, 16);
                invA += __shfl_xor_sync(0xffffffffu, invA, off, 16);
                invB += __shfl_xor_sync(0xffffffffu, invB, off, 16);
                sgnA *= __shfl_xor_sync(0xffffffffu, sgnA, off, 16);
                sgnB *= __shfl_xor_sync(0xffffffffu, sgnB, off, 16);
            }
            if (l == 0 && prev_m0 >= 0) {
                const int g = prev_m0 + 2 * hw;
                out[g]         = (float)sgnA * ((invA & 1) ? -1.f : 1.f);
                out[g + 1]     = (float)sgnB * ((invB & 1) ? -1.f : 1.f);
                out[B + g]     = logA;
                out[B + g + 1] = logB;
            }
        }

        __syncthreads();   // cst top-loads + AB reads complete

        // ---- stage acc -> cst (conflict-free via stride 260) ----
        #pragma unroll
        for (int t = 0; t < 8; t++) {
            #pragma unroll
            for (int e = 0; e < 4; e++) {
                int c = wid * 16 + lq + ((e >> 1) << 3);
                int r = t * 8 + 2 * lr + (e & 1);
                float bv = (e >> 1) ? bias1 : bias0;
                cst[r * CST_MAT + (c >> 4) * 16 + (c & 15)] = acc[t][e] + bv;
            }
        }

        // ---- fill AB for next tile (pre-split) ----
        {
            const int nm0 = nxt * TILE_M;
            #pragma unroll
            for (int it = 0; it < 8; it++) {
                int i = tid + it * BLK;
                int m = i >> 6;
                int k2 = (i & 63) * 2;
                float2 v = *(const float2*)(occ + (size_t)(nm0 + m) * NE + k2);
                uint32_t xh = f2tf(v.x);
                uint32_t xl = f2tf(v.x - __uint_as_float(xh));
                uint32_t yh = f2tf(v.y);
                uint32_t yl = f2tf(v.y - __uint_as_float(yh));
                int idx = m * 128 + (k2 ^ ((m & 7) << 2));
                *(uint4*)&AB[idx] = make_uint4(xh, xl, yh, yl);
            }
        }

        prev_m0 = m0;
        __syncthreads();   // cst(n) + AB(n+1) ready
    }

    // ---- epilogue: LU of the LAST tile ----
    if (prev_m0 >= 0) {
        float a[16], b[16];
        #pragma unroll
        for (int k = 0; k < 16; k++) {
            float d = (k == l) ? 1.f : 0.f;
            a[k] = cst[(2 * hw)     * CST_MAT + k * 16 + l] + d;
            b[k] = cst[(2 * hw + 1) * CST_MAT + k * 16 + l] + d;
        }
        bool  doneA = false,  doneB = false;
        float logA  = 0.f,    logB  = 0.f;
        int   sgnA  = 1,      sgnB  = 1;
        int   pickA = 0,      pickB = 0;
        #pragma unroll
        for (int k = 0; k < 16; k++) {
            uint32_t uA = doneA ? 0u
                : ((__float_as_uint(fabsf(a[k])) & ~0xFu) | (15u - (uint32_t)l));
            uint32_t uB = doneB ? 0u
                : ((__float_as_uint(fabsf(b[k])) & ~0xFu) | (15u - (uint32_t)l));
            #pragma unroll
            for (int off = 8; off; off >>= 1) {
                uint32_t oA = __shfl_xor_sync(0xffffffffu, uA, off, 16);
                uint32_t oB = __shfl_xor_sync(0xffffffffu, uB, off, 16);
                uA = (oA > uA) ? oA : uA;
                uB = (oB > uB) ? oB : uB;
            }
            const int   pA   = 15 - (int)(uA & 15u);
            const int   pB   = 15 - (int)(uB & 15u);
            const float pivA = __shfl_sync(0xffffffffu, a[k], pA, 16);
            const float pivB = __shfl_sync(0xffffffffu, b[k], pB, 16);
            const bool  impA = (l == pA);
            const bool  impB = (l == pB);
            const float mulA = (!doneA && !impA) ? (a[k] / pivA) : 0.f;
            const float mulB = (!doneB && !impB) ? (b[k] / pivB) : 0.f;
            #pragma unroll
            for (int jj = k + 1; jj < 16; jj++) {
                float prA = __shfl_sync(0xffffffffu, a[jj], pA, 16);
                float prB = __shfl_sync(0xffffffffu, b[jj], pB, 16);
                a[jj] -= mulA * prA;
                b[jj] -= mulB * prB;
            }
            if (impA) {
                doneA = true; pickA = k;
                logA += logf(fabsf(pivA));
                if (pivA < 0.f) sgnA = -sgnA;
            }
            if (impB) {
                doneB = true; pickB = k;
                logB += logf(fabsf(pivB));
                if (pivB < 0.f) sgnB = -sgnB;
            }
        }
        int invA = 0, invB = 0;
        #pragma unroll
        for (int t = 0; t < 16; t++) {
            int ptA = __shfl_sync(0xffffffffu, pickA, t, 16);
            int ptB = __shfl_sync(0xffffffffu, pickB, t, 16);
            invA += (t < l && ptA > pickA) ? 1 : 0;
            invB += (t < l && ptB > pickB) ? 1 : 0;
        }
        #pragma unroll
        for (int off = 8; off; off >>= 1) {
            logA += __shfl_xor_sync(0xffffffffu, logA, off, 16);
            logB += __shfl_xor_sync(0xffffffffu, logB, off, 16);
            invA += __shfl_xor_sync(0xffffffffu, invA, off, 16);
            invB += __shfl_xor_sync(0xffffffffu, invB, off, 16);
            sgnA *= __shfl_xor_sync(0xffffffffu, sgnA, off, 16);
            sgnB *= __shfl_xor_sync(0xffffffffu, sgnB, off, 16);
        }
        if (l == 0) {
            const int g = prev_m0 + 2 * hw;
            out[g]         = (float)sgnA * ((invA & 1) ? -1.f : 1.f);
            out[g + 1]     = (float)sgnB * ((invB & 1) ? -1.f : 1.f);
            out[B + g]     = logA;
            out[B + g + 1] = logB;
        }
    }
}

extern "C" void kernel_launch(void* const* d_in, const int* in_sizes, int n_in,
                              void* d_out, int out_size)
{
    const float* occ  = (const float*)d_in[0];   // (B, 128) fp32
    const float* W    = (const float*)d_in[1];   // (128, 256) fp32
    const float* bias = (const float*)d_in[2];   // (256,) fp32
    float* out        = (float*)d_out;           // [sign(B); logabs(B)]
    const int B = in_sizes[0] / NE;

    cudaFuncSetAttribute(jastrow_f2_kernel,
                         cudaFuncAttributeMaxDynamicSharedMemorySize, SMEM_BYTES);
    jastrow_f2_kernel<<<GRID, BLK, SMEM_BYTES>>>(occ, W, bias, out, B);
}